// round 8
// baseline (speedup 1.0000x reference)
#include <cuda_runtime.h>
#include <cuda_bf16.h>
#include <cstdint>

// AddRadiusEdgeIndex: N=8192 points in [0,10]^3, r=1.
// out[0 : N*N)     = masked_dist2 (float32)
// out[N*N : 2*N*N) = edge_mask as 0.0/1.0 float32
//
// Single fused kernel: block = 32 rows x 1024 cols tile, 256 threads,
// 4 cols/thread. Grid = 2048 CTAs: same residency as the 80.4us champion
// (regs 40) but 2x finer work granularity -> smaller finish-skew tail.
// |p|^2 via exact reference fma chain, dist2 via exact rn ops.
// Stores: 2x STG.128 streaming per thread per row. 536 MB -> HBM-write-bound.

#define NPTS  8192
#define ITILE 32
#define JTILE 1024   // 256 threads * 4 cols
#define TPB   256

__global__ void __launch_bounds__(TPB) radius_kernel(const float* __restrict__ pos,
                                                     float* __restrict__ out) {
    __shared__ float4 s_pi[ITILE];

    const int i0 = blockIdx.y * ITILE;
    const int j0 = blockIdx.x * JTILE + threadIdx.x * 4;

    // Load this thread's 4 column points; compute sq with the exact fma chain.
    float4 pj[4];
#pragma unroll
    for (int k = 0; k < 4; k++) {
        const float x = pos[3 * (j0 + k) + 0];
        const float y = pos[3 * (j0 + k) + 1];
        const float z = pos[3 * (j0 + k) + 2];
        float s = __fmul_rn(x, x);
        s = __fmaf_rn(y, y, s);
        s = __fmaf_rn(z, z, s);
        pj[k] = make_float4(x, y, z, s);
    }

    // Row tile into smem: threads 0..31 each build one pi.
    if (threadIdx.x < ITILE) {
        const int i = i0 + threadIdx.x;
        const float x = pos[3 * i + 0];
        const float y = pos[3 * i + 1];
        const float z = pos[3 * i + 2];
        float s = __fmul_rn(x, x);
        s = __fmaf_rn(y, y, s);
        s = __fmaf_rn(z, z, s);
        s_pi[threadIdx.x] = make_float4(x, y, z, s);
    }
    __syncthreads();

    float* od = out + (size_t)i0 * NPTS + j0;
    float* om = od + (size_t)NPTS * NPTS;

#pragma unroll 4
    for (int r = 0; r < ITILE; r++) {
        const float4 pi = s_pi[r];  // broadcast LDS, conflict-free

        float d[4], m[4];
#pragma unroll
        for (int k = 0; k < 4; k++) {
            float dot = __fmul_rn(pi.x, pj[k].x);
            dot = __fmaf_rn(pi.y, pj[k].y, dot);
            dot = __fmaf_rn(pi.z, pj[k].z, dot);
            // (sq_i + sq_j) - 2*dot : exact rounding order, no fma contraction
            float dd = __fsub_rn(__fadd_rn(pi.w, pj[k].w), __fmul_rn(2.0f, dot));
            dd = fmaxf(dd, 0.0f);
            const bool e = (dd <= 1.0f);
            d[k] = e ? dd : 0.0f;
            m[k] = e ? 1.0f : 0.0f;
        }

        __stcs(reinterpret_cast<float4*>(od), make_float4(d[0], d[1], d[2], d[3]));
        __stcs(reinterpret_cast<float4*>(om), make_float4(m[0], m[1], m[2], m[3]));
        od += NPTS;
        om += NPTS;
    }
}

extern "C" void kernel_launch(void* const* d_in, const int* in_sizes, int n_in,
                              void* d_out, int out_size) {
    const float* pos = (const float*)d_in[0];
    float* out = (float*)d_out;

    dim3 grid(NPTS / JTILE, NPTS / ITILE);  // (8, 256) = 2048 CTAs
    radius_kernel<<<grid, TPB>>>(pos, out);
}

// round 9
// speedup vs baseline: 1.3572x; 1.3572x over previous
#include <cuda_runtime.h>
#include <cuda_bf16.h>
#include <cstdint>

// AddRadiusEdgeIndex: N=8192 points in [0,10]^3, r=1.
// out[0 : N*N)     = masked_dist2 (float32)
// out[N*N : 2*N*N) = edge_mask as 0.0/1.0 float32
//
// R3 champion config (64 x 1024 tile, 256 thr, 4 cols/thr, STG.128 streaming)
// with the pj point loads vectorized: 12 floats/thread = 3 aligned LDG.128
// (4x fewer L1 load wavefronts, identical values/arithmetic).

#define NPTS  8192
#define ITILE 64
#define JTILE 1024   // 256 threads * 4 cols
#define TPB   256

__global__ void __launch_bounds__(TPB) radius_kernel(const float* __restrict__ pos,
                                                     float* __restrict__ out) {
    __shared__ float4 s_pi[ITILE];

    const int i0 = blockIdx.y * ITILE;
    const int j0 = blockIdx.x * JTILE + threadIdx.x * 4;

    // 4 consecutive points = 12 contiguous floats, 16B-aligned (48*tid offset).
    const float4* p4 = reinterpret_cast<const float4*>(pos + 3 * (size_t)j0);
    const float4 va = p4[0];
    const float4 vb = p4[1];
    const float4 vc = p4[2];

    float4 pj[4];
    {
        const float px[4] = {va.x, va.w, vb.z, vc.y};
        const float py[4] = {va.y, vb.x, vb.w, vc.z};
        const float pz[4] = {va.z, vb.y, vc.x, vc.w};
#pragma unroll
        for (int k = 0; k < 4; k++) {
            float s = __fmul_rn(px[k], px[k]);
            s = __fmaf_rn(py[k], py[k], s);
            s = __fmaf_rn(pz[k], pz[k], s);
            pj[k] = make_float4(px[k], py[k], pz[k], s);
        }
    }

    // Row tile into smem: threads 0..63 each build one pi (once per block).
    if (threadIdx.x < ITILE) {
        const int i = i0 + threadIdx.x;
        const float x = pos[3 * i + 0];
        const float y = pos[3 * i + 1];
        const float z = pos[3 * i + 2];
        float s = __fmul_rn(x, x);
        s = __fmaf_rn(y, y, s);
        s = __fmaf_rn(z, z, s);
        s_pi[threadIdx.x] = make_float4(x, y, z, s);
    }
    __syncthreads();

    float* od = out + (size_t)i0 * NPTS + j0;
    float* om = od + (size_t)NPTS * NPTS;

#pragma unroll 4
    for (int r = 0; r < ITILE; r++) {
        const float4 pi = s_pi[r];  // broadcast LDS, conflict-free

        float d[4], m[4];
#pragma unroll
        for (int k = 0; k < 4; k++) {
            float dot = __fmul_rn(pi.x, pj[k].x);
            dot = __fmaf_rn(pi.y, pj[k].y, dot);
            dot = __fmaf_rn(pi.z, pj[k].z, dot);
            // (sq_i + sq_j) - 2*dot : exact rounding order, no fma contraction
            float dd = __fsub_rn(__fadd_rn(pi.w, pj[k].w), __fmul_rn(2.0f, dot));
            dd = fmaxf(dd, 0.0f);
            const bool e = (dd <= 1.0f);
            d[k] = e ? dd : 0.0f;
            m[k] = e ? 1.0f : 0.0f;
        }

        __stcs(reinterpret_cast<float4*>(od), make_float4(d[0], d[1], d[2], d[3]));
        __stcs(reinterpret_cast<float4*>(om), make_float4(m[0], m[1], m[2], m[3]));
        od += NPTS;
        om += NPTS;
    }
}

extern "C" void kernel_launch(void* const* d_in, const int* in_sizes, int n_in,
                              void* d_out, int out_size) {
    const float* pos = (const float*)d_in[0];
    float* out = (float*)d_out;

    dim3 grid(NPTS / JTILE, NPTS / ITILE);  // (8, 128) = 1024 CTAs
    radius_kernel<<<grid, TPB>>>(pos, out);
}